// round 9
// baseline (speedup 1.0000x reference)
#include <cuda_runtime.h>
#include <math.h>

#define BB 512
#define TT 200
#define NTOK (BB*TT)          // 102400
#define MIDQ 132
#define NOUTS (BB*(TT-1))     // 101888
#define NQ 10001

// ---------------- scratch (device globals; no allocation) ----------------
__device__ float g_TQ [NQ*192];
__device__ float g_HQ [NQ*MIDQ];
__device__ float g_Tc [201*192];
__device__ float g_Tit[101*192];
__device__ float g_Tut[101*192];
__device__ float g_Tnh[101*192];
__device__ float g_Tna[101*192];
__device__ float g_c0[192], g_s3[192];
__device__ float g_XP[NTOK*192];
__device__ float g_HS[NTOK*64];
__device__ float g_qdisc[NQ], g_qSqd[NQ];
__device__ int4  g_qcls[NQ];

typedef unsigned long long ull;

__device__ __forceinline__ float fsig(float x){ return __fdividef(1.f, 1.f + __expf(-x)); }
__device__ __forceinline__ float tanha(float x){ float y; asm("tanh.approx.f32 %0,%1;" : "=f"(y) : "f"(x)); return y; }
__device__ __forceinline__ float siga(float x){ return fmaf(0.5f, tanha(0.5f*x), 0.5f); }

__device__ __forceinline__ ull pack2(float lo, float hi){
  ull r; asm("mov.b64 %0, {%1,%2};" : "=l"(r) : "f"(lo), "f"(hi)); return r;
}
__device__ __forceinline__ void unpack2(ull v, float& lo, float& hi){
  asm("mov.b64 {%0,%1}, %2;" : "=f"(lo), "=f"(hi) : "l"(v));
}
__device__ __forceinline__ ull ffma2(ull a, ull b, ull c){
  ull d; asm("fma.rn.f32x2 %0, %1, %2, %3;" : "=l"(d) : "l"(a), "l"(b), "l"(c)); return d;
}
__device__ __forceinline__ ull fadd2(ull a, ull b){
  ull d; asm("add.rn.f32x2 %0, %1, %2;" : "=l"(d) : "l"(a), "l"(b)); return d;
}

// ================= P0: fused tables + tq_gemm + hq ==========================
// blocks [0,606): tables; [606,763): TQ gemm; [763,842): HQ
__global__ void p0_kernel(const float* __restrict__ E_q, const float* __restrict__ E_c,
                          const float* __restrict__ E_it, const float* __restrict__ E_ut,
                          const float* __restrict__ E_nh,
                          const float* __restrict__ W_ih, const float* __restrict__ b_ih,
                          const float* __restrict__ W_fuse, const float* __restrict__ b_fuse,
                          const float* __restrict__ qd_W1, const float* __restrict__ qd_b1)
{
  extern __shared__ __align__(16) char ps[];
  int tid = threadIdx.x;
  int blk = blockIdx.x;

  if (blk < 606) {
    float* e_s  = (float*)ps;
    float* tmp_s = e_s + 64;
    int b = blk, g = tid;
    if (b < 201) {
      if (g < 64) e_s[g] = E_c[b*64+g];
      __syncthreads();
      if (g < 192) {
        float acc = 0.f;
        #pragma unroll 8
        for (int k = 0; k < 64; k++) acc = fmaf(W_ih[g*320+64+k], e_s[k], acc);
        g_Tc[b*192+g] = acc;
      }
    } else if (b < 302) {
      int u = b - 201;
      if (g < 64) e_s[g] = E_it[u*64+g];
      __syncthreads();
      if (g < 192) {
        float acc = 0.f;
        #pragma unroll 8
        for (int k = 0; k < 64; k++) acc = fmaf(W_ih[g*320+192+k], e_s[k], acc);
        g_Tit[u*192+g] = acc;
      }
    } else if (b < 605) {
      int which = (b-302)/101, u = (b-302)%101;
      const float* E = (which == 0) ? E_ut : E_nh;
      int off = which*64;
      if (g < 64) e_s[g] = E[u*64+g];
      __syncthreads();
      if (g < 64) {
        float acc = 0.f;
        #pragma unroll 8
        for (int k = 0; k < 64; k++) acc = fmaf(W_fuse[g*192+off+k], e_s[k], acc);
        tmp_s[g] = acc;
      }
      __syncthreads();
      if (g < 192) {
        float acc = 0.f;
        #pragma unroll 8
        for (int d = 0; d < 64; d++) acc = fmaf(W_ih[g*320+256+d], tmp_s[d], acc);
        float* dst = (which == 0) ? g_Tut : (which == 1) ? g_Tnh : g_Tna;
        dst[u*192+g] = acc;
      }
    } else {
      if (g < 192) {
        float acc = b_ih[g], s = 0.f;
        #pragma unroll 8
        for (int d = 0; d < 64; d++) {
          acc = fmaf(W_ih[g*320+256+d], b_fuse[d], acc);
          s += W_ih[g*320+128+d];
        }
        g_c0[g] = acc; g_s3[g] = s;
      }
    }
  } else if (blk < 763) {
    float* Xs  = (float*)ps;        // 32*65
    float* Wsm = Xs + 32*65;        // 32*193
    int tx = tid & 15, ty = tid >> 4;
    int m0 = (blk - 606) * 64;
    float acc[4][12];
    #pragma unroll
    for (int p = 0; p < 4; p++)
      #pragma unroll
      for (int u = 0; u < 12; u++) acc[p][u] = 0.f;

    for (int kb = 0; kb < 64; kb += 32) {
      for (int i = tid; i < 64*32; i += 256) {
        int m = i >> 5, kk = i & 31;
        int row = m0 + m;
        Xs[kk*65+m] = (row < NQ) ? E_q[row*64 + kb + kk] : 0.f;
      }
      for (int i = tid; i < 192*32; i += 256) {
        int nn = i >> 5, kk = i & 31;
        Wsm[kk*193+nn] = W_ih[nn*320 + kb + kk];
      }
      __syncthreads();
      #pragma unroll
      for (int kk = 0; kk < 32; kk++) {
        float a[4], bb[12];
        #pragma unroll
        for (int p = 0; p < 4; p++) a[p] = Xs[kk*65 + ty*4 + p];
        #pragma unroll
        for (int u = 0; u < 12; u++) bb[u] = Wsm[kk*193 + tx*12 + u];
        #pragma unroll
        for (int p = 0; p < 4; p++)
          #pragma unroll
          for (int u = 0; u < 12; u++) acc[p][u] = fmaf(a[p], bb[u], acc[p][u]);
      }
      __syncthreads();
    }
    #pragma unroll
    for (int p = 0; p < 4; p++) {
      int m = m0 + ty*4 + p;
      if (m < NQ) {
        #pragma unroll
        for (int u = 0; u < 12; u++) g_TQ[(size_t)m*192 + tx*12 + u] = acc[p][u];
      }
    }
  } else {
    float* tile = (float*)ps;       // 128*64
    ull w2[32]; float bv = 0.f;
    if (tid < MIDQ) {
      const ull* wr = (const ull*)(qd_W1 + tid*64);
      #pragma unroll
      for (int k = 0; k < 32; k++) w2[k] = wr[k];
      bv = qd_b1[tid];
    }
    int tok0 = (blk - 763) * 128;
    for (int i = tid; i < 128*16; i += 256) {
      int r = i >> 4, c = i & 15;
      int row = tok0 + r; if (row >= NQ) row = NQ-1;
      ((float4*)tile)[r*16 + c] = ((const float4*)(E_q + (size_t)row*64))[c];
    }
    __syncthreads();
    if (tid < MIDQ) {
      for (int r = 0; r < 128; r += 2) {
        if (tok0 + r >= NQ) break;
        const ulonglong2* ha = (const ulonglong2*)(tile + r*64);
        const ulonglong2* hb = (const ulonglong2*)(tile + (r+1)*64);
        ull a0=0ull,a1=0ull,b0=0ull,b1=0ull;
        #pragma unroll
        for (int i2 = 0; i2 < 16; i2++) {
          ulonglong2 pa = ha[i2], pb = hb[i2];
          a0 = ffma2(w2[2*i2],   pa.x, a0);
          a1 = ffma2(w2[2*i2+1], pa.y, a1);
          b0 = ffma2(w2[2*i2],   pb.x, b0);
          b1 = ffma2(w2[2*i2+1], pb.y, b1);
        }
        float p0,p1,p2,p3,q0,q1,q2,q3;
        unpack2(a0,p0,p1); unpack2(a1,p2,p3);
        unpack2(b0,q0,q1); unpack2(b1,q2,q3);
        g_HQ[(size_t)(tok0+r)*MIDQ + tid] = fmaxf(bv + (p0+p1)+(p2+p3), 0.f);
        if (tok0+r+1 < NQ)
          g_HQ[(size_t)(tok0+r+1)*MIDQ + tid] = fmaxf(bv + (q0+q1)+(q2+q3), 0.f);
      }
    }
  }
}

// ---------------- P1b: warp-per-question heads + TQ fold --------------------
__global__ void p1b_kernel(const float* __restrict__ E_q,
                           const float* __restrict__ qd_W2, const float* __restrict__ qd_b2,
                           const float* __restrict__ dc_W1, const float* __restrict__ dc_b1,
                           const float* __restrict__ dc_W2, const float* __restrict__ dc_b2,
                           const int* __restrict__ q2c, const int* __restrict__ q2cm)
{
  __shared__ float dc1s[64*33];
  int tid = threadIdx.x;
  for (int i = tid; i < 32*64; i += 256) { int l = i >> 6, k = i & 63; dc1s[k*33+l] = dc_W1[i]; }
  __syncthreads();
  int lane = tid & 31, wid = tid >> 5;
  int q = blockIdx.x*8 + wid;
  if (q >= NQ) return;

  float h0 = g_HQ[(size_t)q*MIDQ + lane];
  float h1 = g_HQ[(size_t)q*MIDQ + lane + 32];
  float h2 = g_HQ[(size_t)q*MIDQ + lane + 64];
  float h3 = g_HQ[(size_t)q*MIDQ + lane + 96];
  float h4 = (lane < 4) ? g_HQ[(size_t)q*MIDQ + lane + 128] : 0.f;

  int cR = 0, mR = 0;
  if (lane < 4) { cR = q2c[q*4+lane]; mR = q2cm[q*4+lane]; }
  int cls[4], msk[4];
  #pragma unroll
  for (int j = 0; j < 4; j++) { cls[j] = __shfl_sync(0xffffffffu, cR, j); msk[j] = __shfl_sync(0xffffffffu, mR, j); }

  float qd[4];
  #pragma unroll
  for (int j = 0; j < 4; j++) {
    const float* wr = qd_W2 + (size_t)cls[j]*MIDQ;
    float acc = h0*wr[lane] + h1*wr[lane+32] + h2*wr[lane+64] + h3*wr[lane+96];
    if (lane < 4) acc += h4*wr[lane+128];
    #pragma unroll
    for (int o = 16; o > 0; o >>= 1) acc += __shfl_xor_sync(0xffffffffu, acc, o);
    qd[j] = fsig(acc + qd_b2[cls[j]]);
  }

  float dacc = dc_b1[lane];
  #pragma unroll 8
  for (int k = 0; k < 64; k++) dacc = fmaf(dc1s[k*33+lane], E_q[q*64+k], dacc);
  float dv = dc_W2[lane]*fmaxf(dacc, 0.f);
  #pragma unroll
  for (int o = 16; o > 0; o >>= 1) dv += __shfl_xor_sync(0xffffffffu, dv, o);

  float w[4]; float srel = 1e-6f;
  #pragma unroll
  for (int j = 0; j < 4; j++) srel += qd[j]*(float)msk[j];
  #pragma unroll
  for (int j = 0; j < 4; j++) w[j] = qd[j]*(float)msk[j]/srel;
  float S = 0.f; int cl[4];
  #pragma unroll
  for (int j = 0; j < 4; j++) {
    int c = cls[j]; bool fl = (msk[j] != 0);
    for (int j2 = 0; j2 < j; j2++) if (msk[j2] != 0 && cls[j2] == c) fl = false;
    if (fl) { S += qd[j]; cl[j] = c; } else cl[j] = -1;
  }
  if (lane == 0) {
    g_qSqd[q] = S;
    g_qcls[q] = make_int4(cl[0], cl[1], cl[2], cl[3]);
    g_qdisc[q] = fsig(dv + dc_b2[0])*10.f;
  }

  #pragma unroll
  for (int g = 0; g < 6; g++) {
    int o = g*32 + lane;
    float v = g_TQ[(size_t)q*192 + o];
    #pragma unroll
    for (int j = 0; j < 4; j++) v = fmaf(w[j], g_Tc[cls[j]*192 + o], v);
    g_TQ[(size_t)q*192 + o] = v;
  }
}

// ---------------- P2: XP[n] = gather-sum of tables --------------------------
__global__ void xp_kernel(const int* __restrict__ qseq, const int* __restrict__ cseq,
                          const int* __restrict__ itseq, const int* __restrict__ utseq,
                          const int* __restrict__ nhseq, const int* __restrict__ naseq)
{
  __shared__ int qi[32], iti[32], uti[32], nhi[32], nai[32];
  __shared__ float cri[32];
  int tid = threadIdx.x;
  int n0 = blockIdx.x*32;
  int grp = tid >> 5, l = tid & 31;
  if (grp == 0) qi[l]  = qseq [n0+l];
  else if (grp == 1) cri[l] = (float)cseq[n0+l];
  else if (grp == 2) iti[l] = itseq[n0+l];
  else if (grp == 3) uti[l] = utseq[n0+l];
  else if (grp == 4) nhi[l] = nhseq[n0+l];
  else               nai[l] = naseq[n0+l];
  __syncthreads();

  int sub = tid/48, c4 = tid%48;
  float4 s3v = ((const float4*)g_s3)[c4];
  float4 c0v = ((const float4*)g_c0)[c4];
  const float4* TQ4  = (const float4*)g_TQ;
  const float4* Tit4 = (const float4*)g_Tit;
  const float4* Tut4 = (const float4*)g_Tut;
  const float4* Tnh4 = (const float4*)g_Tnh;
  const float4* Tna4 = (const float4*)g_Tna;

  for (int tl = sub; tl < 32; tl += 4) {
    int n = n0 + tl;
    float4 v  = TQ4 [(size_t)qi[tl]*48 + c4];
    float4 a  = Tit4[iti[tl]*48 + c4];
    float4 bu = Tut4[uti[tl]*48 + c4];
    float4 bh = Tnh4[nhi[tl]*48 + c4];
    float4 ba = Tna4[nai[tl]*48 + c4];
    float cr = cri[tl];
    float4 o;
    o.x = v.x + a.x + bu.x + bh.x + ba.x + cr*s3v.x + c0v.x;
    o.y = v.y + a.y + bu.y + bh.y + ba.y + cr*s3v.y + c0v.y;
    o.z = v.z + a.z + bu.z + bh.z + ba.z + cr*s3v.z + c0v.z;
    o.w = v.w + a.w + bu.w + bh.w + ba.w + cr*s3v.w + c0v.w;
    ((float4*)g_XP)[(size_t)n*48 + c4] = o;
  }
}

// ---------------- K4: GRU scan, 4 sequences/block, half-row split -----------
__global__ void __launch_bounds__(384, 1) gru_kernel(const float* __restrict__ W_hh,
                                                     const float* __restrict__ b_hh)
{
  __shared__ __align__(16) float h_s[4][64];
  __shared__ float gh_s[4][192];
  __shared__ float xp_s[4][2][192];       // [seq][buf][row]
  int t = threadIdx.x;
  int r = t >> 1, hh = t & 1;             // row 0..191, half 0/1; pair (t, t^1) intra-warp
  int b0 = blockIdx.x*4;

  ull w2[16];                             // row r, cols hh*32 .. hh*32+31
  const ull* wrow = (const ull*)(W_hh + (size_t)r*64 + hh*32);
  #pragma unroll
  for (int i = 0; i < 16; i++) w2[i] = wrow[i];
  float bv = b_hh[r];

  if (t < 256) h_s[t>>6][t&63] = 0.f;

  // staging role: threads 0..191 stage seqs 0,1 at row t; 192..383 stage 2,3
  int sr = (t < 192) ? t : t - 192;
  int so = (t < 192) ? 0 : 2;
  const float* xpa = g_XP + (size_t)(b0+so  )*TT*192;
  const float* xpb = g_XP + (size_t)(b0+so+1)*TT*192;
  xp_s[so  ][0][sr] = xpa[sr];
  xp_s[so+1][0][sr] = xpb[sr];
  float holdA = xpa[192 + sr];
  float holdB = xpb[192 + sr];

  // gate role: threads 0..255 -> (seq gs, elem ge)
  int gs = t >> 6, ge = t & 63;
  float* hso = g_HS + (size_t)(b0+gs)*TT*64;
  __syncthreads();

  for (int tt = 0; tt < TT; tt++) {
    int tf = (tt+2 < TT) ? tt+2 : TT-1;
    float futA = xpa[(size_t)tf*192 + sr];
    float futB = xpb[(size_t)tf*192 + sr];

    ull a0s0=0ull,a1s0=0ull, a0s1=0ull,a1s1=0ull;
    ull a0s2=0ull,a1s2=0ull, a0s3=0ull,a1s3=0ull;
    const ulonglong2* h0p = (const ulonglong2*)(h_s[0] + hh*32);
    const ulonglong2* h1p = (const ulonglong2*)(h_s[1] + hh*32);
    const ulonglong2* h2p = (const ulonglong2*)(h_s[2] + hh*32);
    const ulonglong2* h3p = (const ulonglong2*)(h_s[3] + hh*32);
    #pragma unroll
    for (int i = 0; i < 8; i++) {
      ulonglong2 p0 = h0p[i], p1 = h1p[i], p2 = h2p[i], p3 = h3p[i];
      a0s0 = ffma2(w2[2*i],   p0.x, a0s0);
      a0s1 = ffma2(w2[2*i],   p1.x, a0s1);
      a0s2 = ffma2(w2[2*i],   p2.x, a0s2);
      a0s3 = ffma2(w2[2*i],   p3.x, a0s3);
      a1s0 = ffma2(w2[2*i+1], p0.y, a1s0);
      a1s1 = ffma2(w2[2*i+1], p1.y, a1s1);
      a1s2 = ffma2(w2[2*i+1], p2.y, a1s2);
      a1s3 = ffma2(w2[2*i+1], p3.y, a1s3);
    }
    // combine halves: packed add, unpack, lane-pair shfl
    {
      ull c0p = fadd2(a0s0, a1s0);
      ull c1p = fadd2(a0s1, a1s1);
      ull c2p = fadd2(a0s2, a1s2);
      ull c3p = fadd2(a0s3, a1s3);
      float x0,y0,x1,y1,x2,y2,x3,y3;
      unpack2(c0p,x0,y0); unpack2(c1p,x1,y1);
      unpack2(c2p,x2,y2); unpack2(c3p,x3,y3);
      float v0 = x0+y0, v1 = x1+y1, v2 = x2+y2, v3 = x3+y3;
      v0 += __shfl_xor_sync(0xffffffffu, v0, 1);
      v1 += __shfl_xor_sync(0xffffffffu, v1, 1);
      v2 += __shfl_xor_sync(0xffffffffu, v2, 1);
      v3 += __shfl_xor_sync(0xffffffffu, v3, 1);
      if (hh == 0) {
        gh_s[0][r] = bv + v0;
        gh_s[1][r] = bv + v1;
        gh_s[2][r] = bv + v2;
        gh_s[3][r] = bv + v3;
      }
    }
    xp_s[so  ][(tt+1)&1][sr] = holdA;
    xp_s[so+1][(tt+1)&1][sr] = holdB;
    __syncthreads();
    if (t < 256) {
      const float* xc = xp_s[gs][tt&1];
      const float* gh = gh_s[gs];
      float rg = siga(xc[ge]      + gh[ge]);
      float zg = siga(xc[64+ge]   + gh[64+ge]);
      float ng = tanha(fmaf(rg, gh[128+ge], xc[128+ge]));
      float hnew = fmaf(zg, h_s[gs][ge] - ng, ng);
      h_s[gs][ge] = hnew;
      hso[(size_t)tt*64 + ge] = hnew;
    }
    holdA = futA; holdB = futB;
    __syncthreads();
  }
}

// ---------------- K5+K6 fused: HL + readout (256 thr, 3 blocks/SM) ----------
__global__ void __launch_bounds__(256, 3) fout_kernel(
                            const float* __restrict__ la_W1, const float* __restrict__ la_b1,
                            const float* __restrict__ la_W2, const float* __restrict__ la_b2,
                            const int* __restrict__ qseq, float* __restrict__ out)
{
  extern __shared__ __align__(16) char sm_[];
  float* Ws = (float*)sm_;                 // [k*132 + row], 64*132 floats
  float* bs = Ws + 64*132;                 // 132 floats (+2 pad)
  ull*   tp = (ull*)(bs + 134);            // [pair*66 + k], 32 pairs
  __shared__ int qv_s[64];                 // qseq[n0+1 .. n0+64]

  int tid = threadIdx.x, lane = tid & 31, wid = tid >> 5;
  int n0 = blockIdx.x * 64;

  if (tid < 64) {
    int idx = n0 + tid + 1; if (idx >= NTOK) idx = NTOK-1;
    qv_s[tid] = qseq[idx];
  }
  for (int i = tid; i < 132*64; i += 256) {
    int row = i >> 6, k = i & 63;
    Ws[k*132 + row] = la_W1[i];
  }
  if (tid < 132) bs[tid] = la_b1[tid];
  for (int i = tid; i < 64*16; i += 256) {
    int tok = i >> 4, c = i & 15;
    float4 v = ((const float4*)(g_HS + (size_t)(n0+tok)*64))[c];
    int p = tok >> 1, e = tok & 1;
    float* base = (float*)&tp[p*66 + 4*c];
    base[0+e] = v.x; base[2+e] = v.y; base[4+e] = v.z; base[6+e] = v.w;
  }
  __syncthreads();

  float b0 = bs[lane], b1v = bs[32+lane], b2v = bs[64+lane], b3v = bs[96+lane];
  float b4v = (lane < 4) ? bs[128+lane] : 0.f;
  ull acc[4][5];
  {
    ull p0=pack2(b0,b0), p1=pack2(b1v,b1v), p2=pack2(b2v,b2v), p3=pack2(b3v,b3v), p4=pack2(b4v,b4v);
    #pragma unroll
    for (int p = 0; p < 4; p++) { acc[p][0]=p0; acc[p][1]=p1; acc[p][2]=p2; acc[p][3]=p3; acc[p][4]=p4; }
  }
  int pbase = wid*4;
  #pragma unroll 4
  for (int k = 0; k < 64; k++) {
    float w0 = Ws[k*132 + lane];
    float w1 = Ws[k*132 + 32 + lane];
    float w2v = Ws[k*132 + 64 + lane];
    float w3 = Ws[k*132 + 96 + lane];
    float w4 = (lane < 4) ? Ws[k*132 + 128 + lane] : 0.f;
    ull d0=pack2(w0,w0), d1=pack2(w1,w1), d2=pack2(w2v,w2v), d3=pack2(w3,w3), d4=pack2(w4,w4);
    #pragma unroll
    for (int p = 0; p < 4; p++) {
      ull hd = tp[(pbase+p)*66 + k];
      acc[p][0] = ffma2(d0, hd, acc[p][0]);
      acc[p][1] = ffma2(d1, hd, acc[p][1]);
      acc[p][2] = ffma2(d2, hd, acc[p][2]);
      acc[p][3] = ffma2(d3, hd, acc[p][3]);
      acc[p][4] = ffma2(d4, hd, acc[p][4]);
    }
  }

  #pragma unroll
  for (int p = 0; p < 4; p++) {
    float va[5], vb[5];
    #pragma unroll
    for (int c = 0; c < 5; c++) {
      unpack2(acc[p][c], va[c], vb[c]);
      va[c] = fmaxf(va[c], 0.f);
      vb[c] = fmaxf(vb[c], 0.f);
    }
    #pragma unroll
    for (int e = 0; e < 2; e++) {
      int lt = (pbase + p)*2 + e;
      int n = n0 + lt;
      int bb = n / TT, it = n - bb*TT;
      if (it == TT-1) continue;
      float v0 = e ? vb[0] : va[0];
      float v1 = e ? vb[1] : va[1];
      float v2 = e ? vb[2] : va[2];
      float v3 = e ? vb[3] : va[3];
      float v4 = e ? vb[4] : va[4];

      int q = qv_s[lt];
      int4 c4 = g_qcls[q];
      int carr[4] = {c4.x, c4.y, c4.z, c4.w};
      float acc4[4];
      #pragma unroll
      for (int jj = 0; jj < 4; jj++) {
        int cc = (carr[jj] < 0) ? 0 : carr[jj];       // dummy row keeps loads uniform
        const float* w2r = la_W2 + (size_t)cc*MIDQ;
        float a = v0*w2r[lane] + v1*w2r[32+lane] + v2*w2r[64+lane] + v3*w2r[96+lane];
        if (lane < 4) a += v4*w2r[128+lane];
        acc4[jj] = a;
      }
      #pragma unroll
      for (int o = 16; o > 0; o >>= 1) {              // ILP-4 interleaved butterflies
        #pragma unroll
        for (int jj = 0; jj < 4; jj++) acc4[jj] += __shfl_xor_sync(0xffffffffu, acc4[jj], o);
      }
      if (lane == 0) {
        float S = 0.f;
        #pragma unroll
        for (int jj = 0; jj < 4; jj++)
          if (carr[jj] >= 0) S += fsig(acc4[jj] + la_b2[carr[jj]]);
        float sq = g_qSqd[q];
        float y = g_qdisc[q]*__fdividef(S - sq, sq + 1e-6f);
        out[bb*(TT-1) + it] = fsig(y);
      }
    }
  }
}

// ---------------- launcher --------------------------------------------------
extern "C" void kernel_launch(void* const* d_in, const int* in_sizes, int n_in,
                              void* d_out, int out_size)
{
  const float* E_q    = (const float*)d_in[0];
  const float* E_c    = (const float*)d_in[1];
  const float* E_it   = (const float*)d_in[2];
  const float* E_ut   = (const float*)d_in[3];
  const float* E_nh   = (const float*)d_in[4];
  const float* W_fuse = (const float*)d_in[5];
  const float* b_fuse = (const float*)d_in[6];
  const float* W_ih   = (const float*)d_in[7];
  const float* b_ih   = (const float*)d_in[8];
  const float* W_hh   = (const float*)d_in[9];
  const float* b_hh   = (const float*)d_in[10];
  const float* qd_W1  = (const float*)d_in[11];
  const float* qd_b1  = (const float*)d_in[12];
  const float* qd_W2  = (const float*)d_in[13];
  const float* qd_b2  = (const float*)d_in[14];
  const float* la_W1  = (const float*)d_in[15];
  const float* la_b1  = (const float*)d_in[16];
  const float* la_W2  = (const float*)d_in[17];
  const float* la_b2  = (const float*)d_in[18];
  const float* dc_W1  = (const float*)d_in[19];
  const float* dc_b1  = (const float*)d_in[20];
  const float* dc_W2  = (const float*)d_in[21];
  const float* dc_b2  = (const float*)d_in[22];

  int off = (in_sizes[23] > 1000000) ? 1 : 0;
  const int* qseq  = (const int*)d_in[23+off];
  const int* cseq  = (const int*)d_in[24+off];
  const int* itseq = (const int*)d_in[25+off];
  const int* utseq = (const int*)d_in[26+off];
  const int* nhseq = (const int*)d_in[27+off];
  const int* naseq = (const int*)d_in[28+off];
  const int* q2c   = (const int*)d_in[29+off];
  const int* q2cm  = (const int*)d_in[30+off];

  const int P0_SMEM = 33024;                          // max(tq 33024, hq 32768)
  const int FOUT_SMEM = (64*132 + 134)*4 + 32*66*8;   // 51224 bytes
  cudaFuncSetAttribute(fout_kernel, cudaFuncAttributeMaxDynamicSharedMemorySize, FOUT_SMEM);

  p0_kernel<<<842, 256, P0_SMEM>>>(E_q, E_c, E_it, E_ut, E_nh,
                                   W_ih, b_ih, W_fuse, b_fuse, qd_W1, qd_b1);
  p1b_kernel<<<(NQ+7)/8, 256>>>(E_q, qd_W2, qd_b2, dc_W1, dc_b1, dc_W2, dc_b2, q2c, q2cm);
  xp_kernel<<<NTOK/32, 192>>>(qseq, cseq, itseq, utseq, nhseq, naseq);
  gru_kernel<<<BB/4, 384>>>(W_hh, b_hh);         // launch #4 -> profiled
  fout_kernel<<<NTOK/64, 256, FOUT_SMEM>>>(la_W1, la_b1, la_W2, la_b2, qseq, (float*)d_out);
}

// round 10
// speedup vs baseline: 1.1568x; 1.1568x over previous
#include <cuda_runtime.h>
#include <math.h>

#define BB 512
#define TT 200
#define NTOK (BB*TT)          // 102400
#define MIDQ 132
#define NOUTS (BB*(TT-1))     // 101888
#define NQ 10001

// ---------------- scratch (device globals; no allocation) ----------------
__device__ float g_TQ [NQ*192];
__device__ float g_HQ [NQ*MIDQ];
__device__ float g_Tc [201*192];
__device__ float g_Tit[101*192];
__device__ float g_Tut[101*192];
__device__ float g_Tnh[101*192];
__device__ float g_Tna[101*192];
__device__ float g_c0[192], g_s3[192];
__device__ float g_XP[NTOK*192];
__device__ float g_HS[NTOK*64];
__device__ float g_qdisc[NQ], g_qSqd[NQ];
__device__ int4  g_qcls[NQ];

typedef unsigned long long ull;

__device__ __forceinline__ float fsig(float x){ return __fdividef(1.f, 1.f + __expf(-x)); }
__device__ __forceinline__ float tanha(float x){ float y; asm("tanh.approx.f32 %0,%1;" : "=f"(y) : "f"(x)); return y; }
__device__ __forceinline__ float siga(float x){ return fmaf(0.5f, tanha(0.5f*x), 0.5f); }

__device__ __forceinline__ ull pack2(float lo, float hi){
  ull r; asm("mov.b64 %0, {%1,%2};" : "=l"(r) : "f"(lo), "f"(hi)); return r;
}
__device__ __forceinline__ void unpack2(ull v, float& lo, float& hi){
  asm("mov.b64 {%0,%1}, %2;" : "=f"(lo), "=f"(hi) : "l"(v));
}
__device__ __forceinline__ ull ffma2(ull a, ull b, ull c){
  ull d; asm("fma.rn.f32x2 %0, %1, %2, %3;" : "=l"(d) : "l"(a), "l"(b), "l"(c)); return d;
}

// ================= P0: fused tables + tq_gemm + hq ==========================
// blocks [0,606): tables; [606,763): TQ gemm; [763,842): HQ
__global__ void p0_kernel(const float* __restrict__ E_q, const float* __restrict__ E_c,
                          const float* __restrict__ E_it, const float* __restrict__ E_ut,
                          const float* __restrict__ E_nh,
                          const float* __restrict__ W_ih, const float* __restrict__ b_ih,
                          const float* __restrict__ W_fuse, const float* __restrict__ b_fuse,
                          const float* __restrict__ qd_W1, const float* __restrict__ qd_b1)
{
  extern __shared__ __align__(16) char ps[];
  int tid = threadIdx.x;
  int blk = blockIdx.x;

  if (blk < 606) {
    float* e_s  = (float*)ps;
    float* tmp_s = e_s + 64;
    int b = blk, g = tid;
    if (b < 201) {
      if (g < 64) e_s[g] = E_c[b*64+g];
      __syncthreads();
      if (g < 192) {
        float acc = 0.f;
        #pragma unroll 8
        for (int k = 0; k < 64; k++) acc = fmaf(W_ih[g*320+64+k], e_s[k], acc);
        g_Tc[b*192+g] = acc;
      }
    } else if (b < 302) {
      int u = b - 201;
      if (g < 64) e_s[g] = E_it[u*64+g];
      __syncthreads();
      if (g < 192) {
        float acc = 0.f;
        #pragma unroll 8
        for (int k = 0; k < 64; k++) acc = fmaf(W_ih[g*320+192+k], e_s[k], acc);
        g_Tit[u*192+g] = acc;
      }
    } else if (b < 605) {
      int which = (b-302)/101, u = (b-302)%101;
      const float* E = (which == 0) ? E_ut : E_nh;
      int off = which*64;
      if (g < 64) e_s[g] = E[u*64+g];
      __syncthreads();
      if (g < 64) {
        float acc = 0.f;
        #pragma unroll 8
        for (int k = 0; k < 64; k++) acc = fmaf(W_fuse[g*192+off+k], e_s[k], acc);
        tmp_s[g] = acc;
      }
      __syncthreads();
      if (g < 192) {
        float acc = 0.f;
        #pragma unroll 8
        for (int d = 0; d < 64; d++) acc = fmaf(W_ih[g*320+256+d], tmp_s[d], acc);
        float* dst = (which == 0) ? g_Tut : (which == 1) ? g_Tnh : g_Tna;
        dst[u*192+g] = acc;
      }
    } else {
      if (g < 192) {
        float acc = b_ih[g], s = 0.f;
        #pragma unroll 8
        for (int d = 0; d < 64; d++) {
          acc = fmaf(W_ih[g*320+256+d], b_fuse[d], acc);
          s += W_ih[g*320+128+d];
        }
        g_c0[g] = acc; g_s3[g] = s;
      }
    }
  } else if (blk < 763) {
    float* Xs  = (float*)ps;        // 32*65
    float* Wsm = Xs + 32*65;        // 32*193
    int tx = tid & 15, ty = tid >> 4;
    int m0 = (blk - 606) * 64;
    float acc[4][12];
    #pragma unroll
    for (int p = 0; p < 4; p++)
      #pragma unroll
      for (int u = 0; u < 12; u++) acc[p][u] = 0.f;

    for (int kb = 0; kb < 64; kb += 32) {
      for (int i = tid; i < 64*32; i += 256) {
        int m = i >> 5, kk = i & 31;
        int row = m0 + m;
        Xs[kk*65+m] = (row < NQ) ? E_q[row*64 + kb + kk] : 0.f;
      }
      for (int i = tid; i < 192*32; i += 256) {
        int nn = i >> 5, kk = i & 31;
        Wsm[kk*193+nn] = W_ih[nn*320 + kb + kk];
      }
      __syncthreads();
      #pragma unroll
      for (int kk = 0; kk < 32; kk++) {
        float a[4], bb[12];
        #pragma unroll
        for (int p = 0; p < 4; p++) a[p] = Xs[kk*65 + ty*4 + p];
        #pragma unroll
        for (int u = 0; u < 12; u++) bb[u] = Wsm[kk*193 + tx*12 + u];
        #pragma unroll
        for (int p = 0; p < 4; p++)
          #pragma unroll
          for (int u = 0; u < 12; u++) acc[p][u] = fmaf(a[p], bb[u], acc[p][u]);
      }
      __syncthreads();
    }
    #pragma unroll
    for (int p = 0; p < 4; p++) {
      int m = m0 + ty*4 + p;
      if (m < NQ) {
        #pragma unroll
        for (int u = 0; u < 12; u++) g_TQ[(size_t)m*192 + tx*12 + u] = acc[p][u];
      }
    }
  } else {
    float* tile = (float*)ps;       // 128*64
    ull w2[32]; float bv = 0.f;
    if (tid < MIDQ) {
      const ull* wr = (const ull*)(qd_W1 + tid*64);
      #pragma unroll
      for (int k = 0; k < 32; k++) w2[k] = wr[k];
      bv = qd_b1[tid];
    }
    int tok0 = (blk - 763) * 128;
    for (int i = tid; i < 128*16; i += 256) {
      int r = i >> 4, c = i & 15;
      int row = tok0 + r; if (row >= NQ) row = NQ-1;
      ((float4*)tile)[r*16 + c] = ((const float4*)(E_q + (size_t)row*64))[c];
    }
    __syncthreads();
    if (tid < MIDQ) {
      for (int r = 0; r < 128; r += 2) {
        if (tok0 + r >= NQ) break;
        const ulonglong2* ha = (const ulonglong2*)(tile + r*64);
        const ulonglong2* hb = (const ulonglong2*)(tile + (r+1)*64);
        ull a0=0ull,a1=0ull,b0=0ull,b1=0ull;
        #pragma unroll
        for (int i2 = 0; i2 < 16; i2++) {
          ulonglong2 pa = ha[i2], pb = hb[i2];
          a0 = ffma2(w2[2*i2],   pa.x, a0);
          a1 = ffma2(w2[2*i2+1], pa.y, a1);
          b0 = ffma2(w2[2*i2],   pb.x, b0);
          b1 = ffma2(w2[2*i2+1], pb.y, b1);
        }
        float p0,p1,p2,p3,q0,q1,q2,q3;
        unpack2(a0,p0,p1); unpack2(a1,p2,p3);
        unpack2(b0,q0,q1); unpack2(b1,q2,q3);
        g_HQ[(size_t)(tok0+r)*MIDQ + tid] = fmaxf(bv + (p0+p1)+(p2+p3), 0.f);
        if (tok0+r+1 < NQ)
          g_HQ[(size_t)(tok0+r+1)*MIDQ + tid] = fmaxf(bv + (q0+q1)+(q2+q3), 0.f);
      }
    }
  }
}

// ---------------- P1b: warp-per-question heads + TQ fold --------------------
__global__ void p1b_kernel(const float* __restrict__ E_q,
                           const float* __restrict__ qd_W2, const float* __restrict__ qd_b2,
                           const float* __restrict__ dc_W1, const float* __restrict__ dc_b1,
                           const float* __restrict__ dc_W2, const float* __restrict__ dc_b2,
                           const int* __restrict__ q2c, const int* __restrict__ q2cm)
{
  __shared__ float dc1s[64*33];
  int tid = threadIdx.x;
  for (int i = tid; i < 32*64; i += 256) { int l = i >> 6, k = i & 63; dc1s[k*33+l] = dc_W1[i]; }
  __syncthreads();
  int lane = tid & 31, wid = tid >> 5;
  int q = blockIdx.x*8 + wid;
  if (q >= NQ) return;

  float h0 = g_HQ[(size_t)q*MIDQ + lane];
  float h1 = g_HQ[(size_t)q*MIDQ + lane + 32];
  float h2 = g_HQ[(size_t)q*MIDQ + lane + 64];
  float h3 = g_HQ[(size_t)q*MIDQ + lane + 96];
  float h4 = (lane < 4) ? g_HQ[(size_t)q*MIDQ + lane + 128] : 0.f;

  int cR = 0, mR = 0;
  if (lane < 4) { cR = q2c[q*4+lane]; mR = q2cm[q*4+lane]; }
  int cls[4], msk[4];
  #pragma unroll
  for (int j = 0; j < 4; j++) { cls[j] = __shfl_sync(0xffffffffu, cR, j); msk[j] = __shfl_sync(0xffffffffu, mR, j); }

  float qd[4];
  #pragma unroll
  for (int j = 0; j < 4; j++) {
    const float* wr = qd_W2 + (size_t)cls[j]*MIDQ;
    float acc = h0*wr[lane] + h1*wr[lane+32] + h2*wr[lane+64] + h3*wr[lane+96];
    if (lane < 4) acc += h4*wr[lane+128];
    #pragma unroll
    for (int o = 16; o > 0; o >>= 1) acc += __shfl_xor_sync(0xffffffffu, acc, o);
    qd[j] = fsig(acc + qd_b2[cls[j]]);
  }

  float dacc = dc_b1[lane];
  #pragma unroll 8
  for (int k = 0; k < 64; k++) dacc = fmaf(dc1s[k*33+lane], E_q[q*64+k], dacc);
  float dv = dc_W2[lane]*fmaxf(dacc, 0.f);
  #pragma unroll
  for (int o = 16; o > 0; o >>= 1) dv += __shfl_xor_sync(0xffffffffu, dv, o);

  float w[4]; float srel = 1e-6f;
  #pragma unroll
  for (int j = 0; j < 4; j++) srel += qd[j]*(float)msk[j];
  #pragma unroll
  for (int j = 0; j < 4; j++) w[j] = qd[j]*(float)msk[j]/srel;
  float S = 0.f; int cl[4];
  #pragma unroll
  for (int j = 0; j < 4; j++) {
    int c = cls[j]; bool fl = (msk[j] != 0);
    for (int j2 = 0; j2 < j; j2++) if (msk[j2] != 0 && cls[j2] == c) fl = false;
    if (fl) { S += qd[j]; cl[j] = c; } else cl[j] = -1;
  }
  if (lane == 0) {
    g_qSqd[q] = S;
    g_qcls[q] = make_int4(cl[0], cl[1], cl[2], cl[3]);
    g_qdisc[q] = fsig(dv + dc_b2[0])*10.f;
  }

  #pragma unroll
  for (int g = 0; g < 6; g++) {
    int o = g*32 + lane;
    float v = g_TQ[(size_t)q*192 + o];
    #pragma unroll
    for (int j = 0; j < 4; j++) v = fmaf(w[j], g_Tc[cls[j]*192 + o], v);
    g_TQ[(size_t)q*192 + o] = v;
  }
}

// ---------------- K4: GRU scan, 2 seq/block, xp gather in prologue ----------
__global__ void __launch_bounds__(192, 2) gru_kernel(
    const float* __restrict__ W_hh, const float* __restrict__ b_hh,
    const int* __restrict__ qseq, const int* __restrict__ cseq,
    const int* __restrict__ itseq, const int* __restrict__ utseq,
    const int* __restrict__ nhseq, const int* __restrict__ naseq)
{
  __shared__ __align__(16) float h_s[2][64];
  __shared__ float gh_s[2][192];
  __shared__ float xp_s[2][2][192];     // [seq][buf][row]
  __shared__ int qs_s[2*TT], it_s[2*TT], ut_s[2*TT], nh_s[2*TT], na_s[2*TT];
  __shared__ float cr_s[2*TT];
  int r = threadIdx.x;
  int bA = blockIdx.x*2, bBv = bA + 1;
  int base = bA*TT;                     // 400 contiguous tokens

  // ---- prologue: stage indices, gather-sum tables into g_XP (L2-hot) ----
  for (int i = r; i < 2*TT; i += 192) {
    qs_s[i] = qseq[base+i];  cr_s[i] = (float)cseq[base+i];
    it_s[i] = itseq[base+i]; ut_s[i] = utseq[base+i];
    nh_s[i] = nhseq[base+i]; na_s[i] = naseq[base+i];
  }
  __syncthreads();
  {
    float s3v = g_s3[r], c0v = g_c0[r];
    float* xpw = g_XP + (size_t)base*192;
    #pragma unroll 1
    for (int tk = 0; tk < 2*TT; tk += 4) {
      float v[4];
      #pragma unroll
      for (int u = 0; u < 4; u++) {
        int j = tk + u;
        float a0 = g_TQ[(size_t)qs_s[j]*192 + r];
        float a1 = g_Tit[it_s[j]*192 + r];
        float a2 = g_Tut[ut_s[j]*192 + r];
        float a3 = g_Tnh[nh_s[j]*192 + r];
        float a4 = g_Tna[na_s[j]*192 + r];
        v[u] = ((a0+a1)+(a2+a3)) + fmaf(cr_s[j], s3v, a4 + c0v);
      }
      #pragma unroll
      for (int u = 0; u < 4; u++) xpw[(size_t)(tk+u)*192 + r] = v[u];
    }
  }
  __syncthreads();

  // ---- main scan (R8 structure) ----
  ull w2[32];
  const ull* wrow = (const ull*)W_hh + (size_t)r*32;
  #pragma unroll
  for (int i = 0; i < 32; i++) w2[i] = wrow[i];
  float bv = b_hh[r];
  if (r < 64) { h_s[0][r] = 0.f; h_s[1][r] = 0.f; }
  const float* xpA = g_XP + (size_t)bA*TT*192;
  const float* xpB = g_XP + (size_t)bBv*TT*192;
  float* hsA = g_HS + (size_t)bA*TT*64;
  float* hsB = g_HS + (size_t)bBv*TT*64;
  xp_s[0][0][r] = xpA[r];
  xp_s[1][0][r] = xpB[r];
  float holdA = xpA[192 + r];
  float holdB = xpB[192 + r];
  __syncthreads();

  for (int t = 0; t < TT; t++) {
    int tf = (t+2 < TT) ? t+2 : TT-1;
    float futA = xpA[(size_t)tf*192 + r];
    float futB = xpB[(size_t)tf*192 + r];

    ull aA0=0ull,aA1=0ull,aA2=0ull,aA3=0ull;
    ull aB0=0ull,aB1=0ull,aB2=0ull,aB3=0ull;
    const ulonglong2* hA = (const ulonglong2*)h_s[0];
    const ulonglong2* hB = (const ulonglong2*)h_s[1];
    #pragma unroll
    for (int i = 0; i < 8; i++) {
      ulonglong2 pA = hA[2*i], qA = hA[2*i+1];
      ulonglong2 pB = hB[2*i], qB = hB[2*i+1];
      aA0 = ffma2(w2[4*i+0], pA.x, aA0);
      aB0 = ffma2(w2[4*i+0], pB.x, aB0);
      aA1 = ffma2(w2[4*i+1], pA.y, aA1);
      aB1 = ffma2(w2[4*i+1], pB.y, aB1);
      aA2 = ffma2(w2[4*i+2], qA.x, aA2);
      aB2 = ffma2(w2[4*i+2], qB.x, aB2);
      aA3 = ffma2(w2[4*i+3], qA.y, aA3);
      aB3 = ffma2(w2[4*i+3], qB.y, aB3);
    }
    {
      float s0,s1,s2,s3,s4,s5,s6,s7;
      unpack2(aA0,s0,s1); unpack2(aA1,s2,s3); unpack2(aA2,s4,s5); unpack2(aA3,s6,s7);
      gh_s[0][r] = bv + (((s0+s1)+(s2+s3)) + ((s4+s5)+(s6+s7)));
      unpack2(aB0,s0,s1); unpack2(aB1,s2,s3); unpack2(aB2,s4,s5); unpack2(aB3,s6,s7);
      gh_s[1][r] = bv + (((s0+s1)+(s2+s3)) + ((s4+s5)+(s6+s7)));
    }
    xp_s[0][(t+1)&1][r] = holdA;
    xp_s[1][(t+1)&1][r] = holdB;
    __syncthreads();
    if (r < 128) {
      int s = r >> 6, e = r & 63;
      const float* xc = xp_s[s][t&1];
      const float* gh = gh_s[s];
      float rg = siga(xc[e]      + gh[e]);
      float zg = siga(xc[64+e]   + gh[64+e]);
      float ng = tanha(fmaf(rg, gh[128+e], xc[128+e]));
      float hnew = fmaf(zg, h_s[s][e] - ng, ng);
      h_s[s][e] = hnew;
      float* hso = s ? hsB : hsA;
      hso[(size_t)t*64 + e] = hnew;
    }
    holdA = futA; holdB = futB;
    __syncthreads();
  }
}

// ---------------- K5+K6 fused: HL + readout (256 thr, 3 blocks/SM) ----------
__global__ void __launch_bounds__(256, 3) fout_kernel(
                            const float* __restrict__ la_W1, const float* __restrict__ la_b1,
                            const float* __restrict__ la_W2, const float* __restrict__ la_b2,
                            const int* __restrict__ qseq, float* __restrict__ out)
{
  extern __shared__ __align__(16) char sm_[];
  float* Ws = (float*)sm_;                 // [k*132 + row], 64*132 floats
  float* bs = Ws + 64*132;                 // 132 floats (+2 pad)
  ull*   tp = (ull*)(bs + 134);            // [pair*66 + k], 32 pairs
  __shared__ int qv_s[64];                 // qseq[n0+1 .. n0+64]

  int tid = threadIdx.x, lane = tid & 31, wid = tid >> 5;
  int n0 = blockIdx.x * 64;

  if (tid < 64) {
    int idx = n0 + tid + 1; if (idx >= NTOK) idx = NTOK-1;
    qv_s[tid] = qseq[idx];
  }
  for (int i = tid; i < 132*64; i += 256) {
    int row = i >> 6, k = i & 63;
    Ws[k*132 + row] = la_W1[i];
  }
  if (tid < 132) bs[tid] = la_b1[tid];
  for (int i = tid; i < 64*16; i += 256) {
    int tok = i >> 4, c = i & 15;
    float4 v = ((const float4*)(g_HS + (size_t)(n0+tok)*64))[c];
    int p = tok >> 1, e = tok & 1;
    float* base = (float*)&tp[p*66 + 4*c];
    base[0+e] = v.x; base[2+e] = v.y; base[4+e] = v.z; base[6+e] = v.w;
  }
  __syncthreads();

  float b0 = bs[lane], b1v = bs[32+lane], b2v = bs[64+lane], b3v = bs[96+lane];
  float b4v = (lane < 4) ? bs[128+lane] : 0.f;
  ull acc[4][5];
  {
    ull p0=pack2(b0,b0), p1=pack2(b1v,b1v), p2=pack2(b2v,b2v), p3=pack2(b3v,b3v), p4=pack2(b4v,b4v);
    #pragma unroll
    for (int p = 0; p < 4; p++) { acc[p][0]=p0; acc[p][1]=p1; acc[p][2]=p2; acc[p][3]=p3; acc[p][4]=p4; }
  }
  int pbase = wid*4;
  #pragma unroll 4
  for (int k = 0; k < 64; k++) {
    float w0 = Ws[k*132 + lane];
    float w1 = Ws[k*132 + 32 + lane];
    float w2v = Ws[k*132 + 64 + lane];
    float w3 = Ws[k*132 + 96 + lane];
    float w4 = (lane < 4) ? Ws[k*132 + 128 + lane] : 0.f;
    ull d0=pack2(w0,w0), d1=pack2(w1,w1), d2=pack2(w2v,w2v), d3=pack2(w3,w3), d4=pack2(w4,w4);
    #pragma unroll
    for (int p = 0; p < 4; p++) {
      ull hd = tp[(pbase+p)*66 + k];
      acc[p][0] = ffma2(d0, hd, acc[p][0]);
      acc[p][1] = ffma2(d1, hd, acc[p][1]);
      acc[p][2] = ffma2(d2, hd, acc[p][2]);
      acc[p][3] = ffma2(d3, hd, acc[p][3]);
      acc[p][4] = ffma2(d4, hd, acc[p][4]);
    }
  }

  #pragma unroll
  for (int p = 0; p < 4; p++) {
    float va[5], vb[5];
    #pragma unroll
    for (int c = 0; c < 5; c++) {
      unpack2(acc[p][c], va[c], vb[c]);
      va[c] = fmaxf(va[c], 0.f);
      vb[c] = fmaxf(vb[c], 0.f);
    }
    #pragma unroll
    for (int e = 0; e < 2; e++) {
      int lt = (pbase + p)*2 + e;
      int n = n0 + lt;
      int bb = n / TT, it = n - bb*TT;
      if (it == TT-1) continue;
      float v0 = e ? vb[0] : va[0];
      float v1 = e ? vb[1] : va[1];
      float v2 = e ? vb[2] : va[2];
      float v3 = e ? vb[3] : va[3];
      float v4 = e ? vb[4] : va[4];

      int q = qv_s[lt];
      int4 c4 = g_qcls[q];
      int carr[4] = {c4.x, c4.y, c4.z, c4.w};
      float acc4[4];
      #pragma unroll
      for (int jj = 0; jj < 4; jj++) {
        int cc = (carr[jj] < 0) ? 0 : carr[jj];       // dummy row keeps loads uniform
        const float* w2r = la_W2 + (size_t)cc*MIDQ;
        float a = v0*w2r[lane] + v1*w2r[32+lane] + v2*w2r[64+lane] + v3*w2r[96+lane];
        if (lane < 4) a += v4*w2r[128+lane];
        acc4[jj] = a;
      }
      #pragma unroll
      for (int o = 16; o > 0; o >>= 1) {              // ILP-4 interleaved butterflies
        #pragma unroll
        for (int jj = 0; jj < 4; jj++) acc4[jj] += __shfl_xor_sync(0xffffffffu, acc4[jj], o);
      }
      if (lane == 0) {
        float S = 0.f;
        #pragma unroll
        for (int jj = 0; jj < 4; jj++)
          if (carr[jj] >= 0) S += fsig(acc4[jj] + la_b2[carr[jj]]);
        float sq = g_qSqd[q];
        float y = g_qdisc[q]*__fdividef(S - sq, sq + 1e-6f);
        out[bb*(TT-1) + it] = fsig(y);
      }
    }
  }
}

// ---------------- launcher --------------------------------------------------
extern "C" void kernel_launch(void* const* d_in, const int* in_sizes, int n_in,
                              void* d_out, int out_size)
{
  const float* E_q    = (const float*)d_in[0];
  const float* E_c    = (const float*)d_in[1];
  const float* E_it   = (const float*)d_in[2];
  const float* E_ut   = (const float*)d_in[3];
  const float* E_nh   = (const float*)d_in[4];
  const float* W_fuse = (const float*)d_in[5];
  const float* b_fuse = (const float*)d_in[6];
  const float* W_ih   = (const float*)d_in[7];
  const float* b_ih   = (const float*)d_in[8];
  const float* W_hh   = (const float*)d_in[9];
  const float* b_hh   = (const float*)d_in[10];
  const float* qd_W1  = (const float*)d_in[11];
  const float* qd_b1  = (const float*)d_in[12];
  const float* qd_W2  = (const float*)d_in[13];
  const float* qd_b2  = (const float*)d_in[14];
  const float* la_W1  = (const float*)d_in[15];
  const float* la_b1  = (const float*)d_in[16];
  const float* la_W2  = (const float*)d_in[17];
  const float* la_b2  = (const float*)d_in[18];
  const float* dc_W1  = (const float*)d_in[19];
  const float* dc_b1  = (const float*)d_in[20];
  const float* dc_W2  = (const float*)d_in[21];
  const float* dc_b2  = (const float*)d_in[22];

  int off = (in_sizes[23] > 1000000) ? 1 : 0;
  const int* qseq  = (const int*)d_in[23+off];
  const int* cseq  = (const int*)d_in[24+off];
  const int* itseq = (const int*)d_in[25+off];
  const int* utseq = (const int*)d_in[26+off];
  const int* nhseq = (const int*)d_in[27+off];
  const int* naseq = (const int*)d_in[28+off];
  const int* q2c   = (const int*)d_in[29+off];
  const int* q2cm  = (const int*)d_in[30+off];

  const int P0_SMEM = 33024;                          // max(tq 33024, hq 32768)
  const int FOUT_SMEM = (64*132 + 134)*4 + 32*66*8;   // 51224 bytes
  cudaFuncSetAttribute(fout_kernel, cudaFuncAttributeMaxDynamicSharedMemorySize, FOUT_SMEM);

  p0_kernel<<<842, 256, P0_SMEM>>>(E_q, E_c, E_it, E_ut, E_nh,
                                   W_ih, b_ih, W_fuse, b_fuse, qd_W1, qd_b1);
  p1b_kernel<<<(NQ+7)/8, 256>>>(E_q, qd_W2, qd_b2, dc_W1, dc_b1, dc_W2, dc_b2, q2c, q2cm);
  gru_kernel<<<BB/2, 192>>>(W_hh, b_hh, qseq, cseq, itseq, utseq, nhseq, naseq);
  fout_kernel<<<NTOK/64, 256, FOUT_SMEM>>>(la_W1, la_b1, la_W2, la_b2, qseq, (float*)d_out);
}

// round 11
// speedup vs baseline: 1.2350x; 1.0676x over previous
#include <cuda_runtime.h>
#include <math.h>

#define BB 512
#define TT 200
#define NTOK (BB*TT)          // 102400
#define MIDQ 132
#define NOUTS (BB*(TT-1))     // 101888
#define NQ 10001

// ---------------- scratch (device globals; no allocation) ----------------
__device__ float g_TQ [NQ*192];
__device__ float g_HQ [NQ*MIDQ];
__device__ float g_Tc [201*192];
__device__ float g_Tit[101*192];
__device__ float g_Tut[101*192];
__device__ float g_Tnh[101*192];
__device__ float g_Tna[101*192];
__device__ float g_c0[192], g_s3[192];
__device__ float g_XP[NTOK*192];
__device__ float g_HS[NTOK*64];
__device__ float g_qdisc[NQ], g_qSqd[NQ];
__device__ int4  g_qcls[NQ];

typedef unsigned long long ull;

__device__ __forceinline__ float fsig(float x){ return __fdividef(1.f, 1.f + __expf(-x)); }
__device__ __forceinline__ float tanha(float x){ float y; asm("tanh.approx.f32 %0,%1;" : "=f"(y) : "f"(x)); return y; }
__device__ __forceinline__ float siga(float x){ return fmaf(0.5f, tanha(0.5f*x), 0.5f); }

__device__ __forceinline__ ull pack2(float lo, float hi){
  ull r; asm("mov.b64 %0, {%1,%2};" : "=l"(r) : "f"(lo), "f"(hi)); return r;
}
__device__ __forceinline__ void unpack2(ull v, float& lo, float& hi){
  asm("mov.b64 {%0,%1}, %2;" : "=f"(lo), "=f"(hi) : "l"(v));
}
__device__ __forceinline__ ull ffma2(ull a, ull b, ull c){
  ull d; asm("fma.rn.f32x2 %0, %1, %2, %3;" : "=l"(d) : "l"(a), "l"(b), "l"(c)); return d;
}
__device__ __forceinline__ void cpasync4(unsigned smem, const void* g){
  asm volatile("cp.async.ca.shared.global [%0], [%1], 4;" :: "r"(smem), "l"(g));
}

// ================= P0: fused tables + tq_gemm + hq ==========================
// blocks [0,606): tables; [606,763): TQ gemm; [763,842): HQ
__global__ void p0_kernel(const float* __restrict__ E_q, const float* __restrict__ E_c,
                          const float* __restrict__ E_it, const float* __restrict__ E_ut,
                          const float* __restrict__ E_nh,
                          const float* __restrict__ W_ih, const float* __restrict__ b_ih,
                          const float* __restrict__ W_fuse, const float* __restrict__ b_fuse,
                          const float* __restrict__ qd_W1, const float* __restrict__ qd_b1)
{
  extern __shared__ __align__(16) char ps[];
  int tid = threadIdx.x;
  int blk = blockIdx.x;

  if (blk < 606) {
    float* e_s  = (float*)ps;
    float* tmp_s = e_s + 64;
    int b = blk, g = tid;
    if (b < 201) {
      if (g < 64) e_s[g] = E_c[b*64+g];
      __syncthreads();
      if (g < 192) {
        float acc = 0.f;
        #pragma unroll 8
        for (int k = 0; k < 64; k++) acc = fmaf(W_ih[g*320+64+k], e_s[k], acc);
        g_Tc[b*192+g] = acc;
      }
    } else if (b < 302) {
      int u = b - 201;
      if (g < 64) e_s[g] = E_it[u*64+g];
      __syncthreads();
      if (g < 192) {
        float acc = 0.f;
        #pragma unroll 8
        for (int k = 0; k < 64; k++) acc = fmaf(W_ih[g*320+192+k], e_s[k], acc);
        g_Tit[u*192+g] = acc;
      }
    } else if (b < 605) {
      int which = (b-302)/101, u = (b-302)%101;
      const float* E = (which == 0) ? E_ut : E_nh;
      int off = which*64;
      if (g < 64) e_s[g] = E[u*64+g];
      __syncthreads();
      if (g < 64) {
        float acc = 0.f;
        #pragma unroll 8
        for (int k = 0; k < 64; k++) acc = fmaf(W_fuse[g*192+off+k], e_s[k], acc);
        tmp_s[g] = acc;
      }
      __syncthreads();
      if (g < 192) {
        float acc = 0.f;
        #pragma unroll 8
        for (int d = 0; d < 64; d++) acc = fmaf(W_ih[g*320+256+d], tmp_s[d], acc);
        float* dst = (which == 0) ? g_Tut : (which == 1) ? g_Tnh : g_Tna;
        dst[u*192+g] = acc;
      }
    } else {
      if (g < 192) {
        float acc = b_ih[g], s = 0.f;
        #pragma unroll 8
        for (int d = 0; d < 64; d++) {
          acc = fmaf(W_ih[g*320+256+d], b_fuse[d], acc);
          s += W_ih[g*320+128+d];
        }
        g_c0[g] = acc; g_s3[g] = s;
      }
    }
  } else if (blk < 763) {
    float* Xs  = (float*)ps;        // 32*65
    float* Wsm = Xs + 32*65;        // 32*193
    int tx = tid & 15, ty = tid >> 4;
    int m0 = (blk - 606) * 64;
    float acc[4][12];
    #pragma unroll
    for (int p = 0; p < 4; p++)
      #pragma unroll
      for (int u = 0; u < 12; u++) acc[p][u] = 0.f;

    for (int kb = 0; kb < 64; kb += 32) {
      for (int i = tid; i < 64*32; i += 256) {
        int m = i >> 5, kk = i & 31;
        int row = m0 + m;
        Xs[kk*65+m] = (row < NQ) ? E_q[row*64 + kb + kk] : 0.f;
      }
      for (int i = tid; i < 192*32; i += 256) {
        int nn = i >> 5, kk = i & 31;
        Wsm[kk*193+nn] = W_ih[nn*320 + kb + kk];
      }
      __syncthreads();
      #pragma unroll
      for (int kk = 0; kk < 32; kk++) {
        float a[4], bb[12];
        #pragma unroll
        for (int p = 0; p < 4; p++) a[p] = Xs[kk*65 + ty*4 + p];
        #pragma unroll
        for (int u = 0; u < 12; u++) bb[u] = Wsm[kk*193 + tx*12 + u];
        #pragma unroll
        for (int p = 0; p < 4; p++)
          #pragma unroll
          for (int u = 0; u < 12; u++) acc[p][u] = fmaf(a[p], bb[u], acc[p][u]);
      }
      __syncthreads();
    }
    #pragma unroll
    for (int p = 0; p < 4; p++) {
      int m = m0 + ty*4 + p;
      if (m < NQ) {
        #pragma unroll
        for (int u = 0; u < 12; u++) g_TQ[(size_t)m*192 + tx*12 + u] = acc[p][u];
      }
    }
  } else {
    float* tile = (float*)ps;       // 128*64
    ull w2[32]; float bv = 0.f;
    if (tid < MIDQ) {
      const ull* wr = (const ull*)(qd_W1 + tid*64);
      #pragma unroll
      for (int k = 0; k < 32; k++) w2[k] = wr[k];
      bv = qd_b1[tid];
    }
    int tok0 = (blk - 763) * 128;
    for (int i = tid; i < 128*16; i += 256) {
      int r = i >> 4, c = i & 15;
      int row = tok0 + r; if (row >= NQ) row = NQ-1;
      ((float4*)tile)[r*16 + c] = ((const float4*)(E_q + (size_t)row*64))[c];
    }
    __syncthreads();
    if (tid < MIDQ) {
      for (int r = 0; r < 128; r += 2) {
        if (tok0 + r >= NQ) break;
        const ulonglong2* ha = (const ulonglong2*)(tile + r*64);
        const ulonglong2* hb = (const ulonglong2*)(tile + (r+1)*64);
        ull a0=0ull,a1=0ull,b0=0ull,b1=0ull;
        #pragma unroll
        for (int i2 = 0; i2 < 16; i2++) {
          ulonglong2 pa = ha[i2], pb = hb[i2];
          a0 = ffma2(w2[2*i2],   pa.x, a0);
          a1 = ffma2(w2[2*i2+1], pa.y, a1);
          b0 = ffma2(w2[2*i2],   pb.x, b0);
          b1 = ffma2(w2[2*i2+1], pb.y, b1);
        }
        float p0,p1,p2,p3,q0,q1,q2,q3;
        unpack2(a0,p0,p1); unpack2(a1,p2,p3);
        unpack2(b0,q0,q1); unpack2(b1,q2,q3);
        g_HQ[(size_t)(tok0+r)*MIDQ + tid] = fmaxf(bv + (p0+p1)+(p2+p3), 0.f);
        if (tok0+r+1 < NQ)
          g_HQ[(size_t)(tok0+r+1)*MIDQ + tid] = fmaxf(bv + (q0+q1)+(q2+q3), 0.f);
      }
    }
  }
}

// ---------------- P1b: warp-per-question heads + TQ fold --------------------
__global__ void p1b_kernel(const float* __restrict__ E_q,
                           const float* __restrict__ qd_W2, const float* __restrict__ qd_b2,
                           const float* __restrict__ dc_W1, const float* __restrict__ dc_b1,
                           const float* __restrict__ dc_W2, const float* __restrict__ dc_b2,
                           const int* __restrict__ q2c, const int* __restrict__ q2cm)
{
  __shared__ float dc1s[64*33];
  int tid = threadIdx.x;
  for (int i = tid; i < 32*64; i += 256) { int l = i >> 6, k = i & 63; dc1s[k*33+l] = dc_W1[i]; }
  __syncthreads();
  int lane = tid & 31, wid = tid >> 5;
  int q = blockIdx.x*8 + wid;
  if (q >= NQ) return;

  float h0 = g_HQ[(size_t)q*MIDQ + lane];
  float h1 = g_HQ[(size_t)q*MIDQ + lane + 32];
  float h2 = g_HQ[(size_t)q*MIDQ + lane + 64];
  float h3 = g_HQ[(size_t)q*MIDQ + lane + 96];
  float h4 = (lane < 4) ? g_HQ[(size_t)q*MIDQ + lane + 128] : 0.f;

  int cR = 0, mR = 0;
  if (lane < 4) { cR = q2c[q*4+lane]; mR = q2cm[q*4+lane]; }
  int cls[4], msk[4];
  #pragma unroll
  for (int j = 0; j < 4; j++) { cls[j] = __shfl_sync(0xffffffffu, cR, j); msk[j] = __shfl_sync(0xffffffffu, mR, j); }

  float qd[4];
  #pragma unroll
  for (int j = 0; j < 4; j++) {
    const float* wr = qd_W2 + (size_t)cls[j]*MIDQ;
    float acc = h0*wr[lane] + h1*wr[lane+32] + h2*wr[lane+64] + h3*wr[lane+96];
    if (lane < 4) acc += h4*wr[lane+128];
    #pragma unroll
    for (int o = 16; o > 0; o >>= 1) acc += __shfl_xor_sync(0xffffffffu, acc, o);
    qd[j] = fsig(acc + qd_b2[cls[j]]);
  }

  float dacc = dc_b1[lane];
  #pragma unroll 8
  for (int k = 0; k < 64; k++) dacc = fmaf(dc1s[k*33+lane], E_q[q*64+k], dacc);
  float dv = dc_W2[lane]*fmaxf(dacc, 0.f);
  #pragma unroll
  for (int o = 16; o > 0; o >>= 1) dv += __shfl_xor_sync(0xffffffffu, dv, o);

  float w[4]; float srel = 1e-6f;
  #pragma unroll
  for (int j = 0; j < 4; j++) srel += qd[j]*(float)msk[j];
  #pragma unroll
  for (int j = 0; j < 4; j++) w[j] = qd[j]*(float)msk[j]/srel;
  float S = 0.f; int cl[4];
  #pragma unroll
  for (int j = 0; j < 4; j++) {
    int c = cls[j]; bool fl = (msk[j] != 0);
    for (int j2 = 0; j2 < j; j2++) if (msk[j2] != 0 && cls[j2] == c) fl = false;
    if (fl) { S += qd[j]; cl[j] = c; } else cl[j] = -1;
  }
  if (lane == 0) {
    g_qSqd[q] = S;
    g_qcls[q] = make_int4(cl[0], cl[1], cl[2], cl[3]);
    g_qdisc[q] = fsig(dv + dc_b2[0])*10.f;
  }

  #pragma unroll
  for (int g = 0; g < 6; g++) {
    int o = g*32 + lane;
    float v = g_TQ[(size_t)q*192 + o];
    #pragma unroll
    for (int j = 0; j < 4; j++) v = fmaf(w[j], g_Tc[cls[j]*192 + o], v);
    g_TQ[(size_t)q*192 + o] = v;
  }
}

// ---------------- P2: XP[n] = gather-sum of tables --------------------------
__global__ void xp_kernel(const int* __restrict__ qseq, const int* __restrict__ cseq,
                          const int* __restrict__ itseq, const int* __restrict__ utseq,
                          const int* __restrict__ nhseq, const int* __restrict__ naseq)
{
  __shared__ int qi[32], iti[32], uti[32], nhi[32], nai[32];
  __shared__ float cri[32];
  int tid = threadIdx.x;
  int n0 = blockIdx.x*32;
  int grp = tid >> 5, l = tid & 31;
  if (grp == 0) qi[l]  = qseq [n0+l];
  else if (grp == 1) cri[l] = (float)cseq[n0+l];
  else if (grp == 2) iti[l] = itseq[n0+l];
  else if (grp == 3) uti[l] = utseq[n0+l];
  else if (grp == 4) nhi[l] = nhseq[n0+l];
  else               nai[l] = naseq[n0+l];
  __syncthreads();

  int sub = tid/48, c4 = tid%48;
  float4 s3v = ((const float4*)g_s3)[c4];
  float4 c0v = ((const float4*)g_c0)[c4];
  const float4* TQ4  = (const float4*)g_TQ;
  const float4* Tit4 = (const float4*)g_Tit;
  const float4* Tut4 = (const float4*)g_Tut;
  const float4* Tnh4 = (const float4*)g_Tnh;
  const float4* Tna4 = (const float4*)g_Tna;

  for (int tl = sub; tl < 32; tl += 4) {
    int n = n0 + tl;
    float4 v  = TQ4 [(size_t)qi[tl]*48 + c4];
    float4 a  = Tit4[iti[tl]*48 + c4];
    float4 bu = Tut4[uti[tl]*48 + c4];
    float4 bh = Tnh4[nhi[tl]*48 + c4];
    float4 ba = Tna4[nai[tl]*48 + c4];
    float cr = cri[tl];
    float4 o;
    o.x = v.x + a.x + bu.x + bh.x + ba.x + cr*s3v.x + c0v.x;
    o.y = v.y + a.y + bu.y + bh.y + ba.y + cr*s3v.y + c0v.y;
    o.z = v.z + a.z + bu.z + bh.z + ba.z + cr*s3v.z + c0v.z;
    o.w = v.w + a.w + bu.w + bh.w + ba.w + cr*s3v.w + c0v.w;
    ((float4*)g_XP)[(size_t)n*48 + c4] = o;
  }
}

// ---------------- K4: GRU scan, 2 seq/block, cp.async xp pipeline -----------
__global__ void __launch_bounds__(192, 2) gru_kernel(const float* __restrict__ W_hh,
                                                     const float* __restrict__ b_hh)
{
  __shared__ __align__(16) float h_s[2][64];
  __shared__ float gh_s[2][192];
  __shared__ float xp_s[2][4][192];     // [seq][ring][row]
  int r = threadIdx.x;
  int bA = blockIdx.x*2, bBv = bA + 1;
  ull w2[32];
  const ull* wrow = (const ull*)W_hh + (size_t)r*32;
  #pragma unroll
  for (int i = 0; i < 32; i++) w2[i] = wrow[i];
  float bv = b_hh[r];
  if (r < 64) { h_s[0][r] = 0.f; h_s[1][r] = 0.f; }
  const float* xpA = g_XP + (size_t)bA*TT*192 + r;
  const float* xpB = g_XP + (size_t)bBv*TT*192 + r;
  float* hsA = g_HS + (size_t)bA*TT*64;
  float* hsB = g_HS + (size_t)bBv*TT*64;
  unsigned smA = (unsigned)__cvta_generic_to_shared(&xp_s[0][0][r]);
  unsigned smB = (unsigned)__cvta_generic_to_shared(&xp_s[1][0][r]);

  // prologue: issue groups for t = 0,1,2
  #pragma unroll
  for (int k = 0; k < 3; k++) {
    cpasync4(smA + k*192*4, xpA + (size_t)k*192);
    cpasync4(smB + k*192*4, xpB + (size_t)k*192);
    asm volatile("cp.async.commit_group;" ::: "memory");
  }
  __syncthreads();   // h_s visibility

  for (int t = 0; t < TT; t++) {
    asm volatile("cp.async.wait_group 2;" ::: "memory");   // group t landed

    // issue group for t+3 into slot (t+3)&3 (last read at t-1, barrier-safe)
    {
      int tf = (t+3 < TT) ? t+3 : TT-1;
      int sl = (t+3) & 3;
      cpasync4(smA + sl*192*4, xpA + (size_t)tf*192);
      cpasync4(smB + sl*192*4, xpB + (size_t)tf*192);
      asm volatile("cp.async.commit_group;" ::: "memory");
    }

    ull aA0=0ull,aA1=0ull,aA2=0ull,aA3=0ull;
    ull aB0=0ull,aB1=0ull,aB2=0ull,aB3=0ull;
    const ulonglong2* hA = (const ulonglong2*)h_s[0];
    const ulonglong2* hB = (const ulonglong2*)h_s[1];
    #pragma unroll
    for (int i = 0; i < 8; i++) {
      ulonglong2 pA = hA[2*i], qA = hA[2*i+1];
      ulonglong2 pB = hB[2*i], qB = hB[2*i+1];
      aA0 = ffma2(w2[4*i+0], pA.x, aA0);
      aB0 = ffma2(w2[4*i+0], pB.x, aB0);
      aA1 = ffma2(w2[4*i+1], pA.y, aA1);
      aB1 = ffma2(w2[4*i+1], pB.y, aB1);
      aA2 = ffma2(w2[4*i+2], qA.x, aA2);
      aB2 = ffma2(w2[4*i+2], qB.x, aB2);
      aA3 = ffma2(w2[4*i+3], qA.y, aA3);
      aB3 = ffma2(w2[4*i+3], qB.y, aB3);
    }
    {
      float s0,s1,s2,s3,s4,s5,s6,s7;
      unpack2(aA0,s0,s1); unpack2(aA1,s2,s3); unpack2(aA2,s4,s5); unpack2(aA3,s6,s7);
      gh_s[0][r] = bv + (((s0+s1)+(s2+s3)) + ((s4+s5)+(s6+s7)));
      unpack2(aB0,s0,s1); unpack2(aB1,s2,s3); unpack2(aB2,s4,s5); unpack2(aB3,s6,s7);
      gh_s[1][r] = bv + (((s0+s1)+(s2+s3)) + ((s4+s5)+(s6+s7)));
    }
    __syncthreads();   // gh ready + xp slot t visible to all
    if (r < 128) {
      int s = r >> 6, e = r & 63;
      const float* xc = xp_s[s][t & 3];
      const float* gh = gh_s[s];
      float rg = siga(xc[e]      + gh[e]);
      float zg = siga(xc[64+e]   + gh[64+e]);
      float ng = tanha(fmaf(rg, gh[128+e], xc[128+e]));
      float hnew = fmaf(zg, h_s[s][e] - ng, ng);
      h_s[s][e] = hnew;
      float* hso = s ? hsB : hsA;
      hso[(size_t)t*64 + e] = hnew;
    }
    __syncthreads();   // h ready for next matvec; xp slot reads done
  }
}

// ---------------- K5+K6 fused: HL + readout (256 thr, 3 blocks/SM) ----------
__global__ void __launch_bounds__(256, 3) fout_kernel(
                            const float* __restrict__ la_W1, const float* __restrict__ la_b1,
                            const float* __restrict__ la_W2, const float* __restrict__ la_b2,
                            const int* __restrict__ qseq, float* __restrict__ out)
{
  extern __shared__ __align__(16) char sm_[];
  float* Ws = (float*)sm_;                 // [k*132 + row], 64*132 floats
  float* bs = Ws + 64*132;                 // 132 floats (+2 pad)
  ull*   tp = (ull*)(bs + 134);            // [pair*66 + k], 32 pairs
  __shared__ int qv_s[64];                 // qseq[n0+1 .. n0+64]

  int tid = threadIdx.x, lane = tid & 31, wid = tid >> 5;
  int n0 = blockIdx.x * 64;

  if (tid < 64) {
    int idx = n0 + tid + 1; if (idx >= NTOK) idx = NTOK-1;
    qv_s[tid] = qseq[idx];
  }
  for (int i = tid; i < 132*64; i += 256) {
    int row = i >> 6, k = i & 63;
    Ws[k*132 + row] = la_W1[i];
  }
  if (tid < 132) bs[tid] = la_b1[tid];
  for (int i = tid; i < 64*16; i += 256) {
    int tok = i >> 4, c = i & 15;
    float4 v = ((const float4*)(g_HS + (size_t)(n0+tok)*64))[c];
    int p = tok >> 1, e = tok & 1;
    float* base = (float*)&tp[p*66 + 4*c];
    base[0+e] = v.x; base[2+e] = v.y; base[4+e] = v.z; base[6+e] = v.w;
  }
  __syncthreads();

  float b0 = bs[lane], b1v = bs[32+lane], b2v = bs[64+lane], b3v = bs[96+lane];
  float b4v = (lane < 4) ? bs[128+lane] : 0.f;
  ull acc[4][5];
  {
    ull p0=pack2(b0,b0), p1=pack2(b1v,b1v), p2=pack2(b2v,b2v), p3=pack2(b3v,b3v), p4=pack2(b4v,b4v);
    #pragma unroll
    for (int p = 0; p < 4; p++) { acc[p][0]=p0; acc[p][1]=p1; acc[p][2]=p2; acc[p][3]=p3; acc[p][4]=p4; }
  }
  int pbase = wid*4;
  #pragma unroll 4
  for (int k = 0; k < 64; k++) {
    float w0 = Ws[k*132 + lane];
    float w1 = Ws[k*132 + 32 + lane];
    float w2v = Ws[k*132 + 64 + lane];
    float w3 = Ws[k*132 + 96 + lane];
    float w4 = (lane < 4) ? Ws[k*132 + 128 + lane] : 0.f;
    ull d0=pack2(w0,w0), d1=pack2(w1,w1), d2=pack2(w2v,w2v), d3=pack2(w3,w3), d4=pack2(w4,w4);
    #pragma unroll
    for (int p = 0; p < 4; p++) {
      ull hd = tp[(pbase+p)*66 + k];
      acc[p][0] = ffma2(d0, hd, acc[p][0]);
      acc[p][1] = ffma2(d1, hd, acc[p][1]);
      acc[p][2] = ffma2(d2, hd, acc[p][2]);
      acc[p][3] = ffma2(d3, hd, acc[p][3]);
      acc[p][4] = ffma2(d4, hd, acc[p][4]);
    }
  }

  #pragma unroll
  for (int p = 0; p < 4; p++) {
    float va[5], vb[5];
    #pragma unroll
    for (int c = 0; c < 5; c++) {
      unpack2(acc[p][c], va[c], vb[c]);
      va[c] = fmaxf(va[c], 0.f);
      vb[c] = fmaxf(vb[c], 0.f);
    }
    #pragma unroll
    for (int e = 0; e < 2; e++) {
      int lt = (pbase + p)*2 + e;
      int n = n0 + lt;
      int bb = n / TT, it = n - bb*TT;
      if (it == TT-1) continue;
      float v0 = e ? vb[0] : va[0];
      float v1 = e ? vb[1] : va[1];
      float v2 = e ? vb[2] : va[2];
      float v3 = e ? vb[3] : va[3];
      float v4 = e ? vb[4] : va[4];

      int q = qv_s[lt];
      int4 c4 = g_qcls[q];
      int carr[4] = {c4.x, c4.y, c4.z, c4.w};
      float acc4[4];
      #pragma unroll
      for (int jj = 0; jj < 4; jj++) {
        int cc = (carr[jj] < 0) ? 0 : carr[jj];       // dummy row keeps loads uniform
        const float* w2r = la_W2 + (size_t)cc*MIDQ;
        float a = v0*w2r[lane] + v1*w2r[32+lane] + v2*w2r[64+lane] + v3*w2r[96+lane];
        if (lane < 4) a += v4*w2r[128+lane];
        acc4[jj] = a;
      }
      #pragma unroll
      for (int o = 16; o > 0; o >>= 1) {              // ILP-4 interleaved butterflies
        #pragma unroll
        for (int jj = 0; jj < 4; jj++) acc4[jj] += __shfl_xor_sync(0xffffffffu, acc4[jj], o);
      }
      if (lane == 0) {
        float S = 0.f;
        #pragma unroll
        for (int jj = 0; jj < 4; jj++)
          if (carr[jj] >= 0) S += fsig(acc4[jj] + la_b2[carr[jj]]);
        float sq = g_qSqd[q];
        float y = g_qdisc[q]*__fdividef(S - sq, sq + 1e-6f);
        out[bb*(TT-1) + it] = fsig(y);
      }
    }
  }
}

// ---------------- launcher --------------------------------------------------
extern "C" void kernel_launch(void* const* d_in, const int* in_sizes, int n_in,
                              void* d_out, int out_size)
{
  const float* E_q    = (const float*)d_in[0];
  const float* E_c    = (const float*)d_in[1];
  const float* E_it   = (const float*)d_in[2];
  const float* E_ut   = (const float*)d_in[3];
  const float* E_nh   = (const float*)d_in[4];
  const float* W_fuse = (const float*)d_in[5];
  const float* b_fuse = (const float*)d_in[6];
  const float* W_ih   = (const float*)d_in[7];
  const float* b_ih   = (const float*)d_in[8];
  const float* W_hh   = (const float*)d_in[9];
  const float* b_hh   = (const float*)d_in[10];
  const float* qd_W1  = (const float*)d_in[11];
  const float* qd_b1  = (const float*)d_in[12];
  const float* qd_W2  = (const float*)d_in[13];
  const float* qd_b2  = (const float*)d_in[14];
  const float* la_W1  = (const float*)d_in[15];
  const float* la_b1  = (const float*)d_in[16];
  const float* la_W2  = (const float*)d_in[17];
  const float* la_b2  = (const float*)d_in[18];
  const float* dc_W1  = (const float*)d_in[19];
  const float* dc_b1  = (const float*)d_in[20];
  const float* dc_W2  = (const float*)d_in[21];
  const float* dc_b2  = (const float*)d_in[22];

  int off = (in_sizes[23] > 1000000) ? 1 : 0;
  const int* qseq  = (const int*)d_in[23+off];
  const int* cseq  = (const int*)d_in[24+off];
  const int* itseq = (const int*)d_in[25+off];
  const int* utseq = (const int*)d_in[26+off];
  const int* nhseq = (const int*)d_in[27+off];
  const int* naseq = (const int*)d_in[28+off];
  const int* q2c   = (const int*)d_in[29+off];
  const int* q2cm  = (const int*)d_in[30+off];

  const int P0_SMEM = 33024;                          // max(tq 33024, hq 32768)
  const int FOUT_SMEM = (64*132 + 134)*4 + 32*66*8;   // 51224 bytes
  cudaFuncSetAttribute(fout_kernel, cudaFuncAttributeMaxDynamicSharedMemorySize, FOUT_SMEM);

  p0_kernel<<<842, 256, P0_SMEM>>>(E_q, E_c, E_it, E_ut, E_nh,
                                   W_ih, b_ih, W_fuse, b_fuse, qd_W1, qd_b1);
  p1b_kernel<<<(NQ+7)/8, 256>>>(E_q, qd_W2, qd_b2, dc_W1, dc_b1, dc_W2, dc_b2, q2c, q2cm);
  xp_kernel<<<NTOK/32, 192>>>(qseq, cseq, itseq, utseq, nhseq, naseq);
  gru_kernel<<<BB/2, 192>>>(W_hh, b_hh);         // launch #4 -> profiled
  fout_kernel<<<NTOK/64, 256, FOUT_SMEM>>>(la_W1, la_b1, la_W2, la_b2, qseq, (float*)d_out);
}